// round 13
// baseline (speedup 1.0000x reference)
#include <cuda_runtime.h>
#include <cuda_fp16.h>

#define HD   160
#define PLN  25600          // W*D
#define VOL  4096000        // H*W*D
#define NVOX 8192000ULL     // 2*160^3
#define WSEG 80             // passDW w-outputs per block
#define NR   90             // rows processed per passDW block (WSEG + 10)
#define PRE  4              // smem prefetch depth (rows)
#define RING 6              // smem row-ring slots
#define SEG  80             // passH slide segment
#define NBBC 640            // passH grid blocks: 2*160*2

// Normalized 1D Gaussian, KS=11, sigma=1.5
__device__ constexpr float GW[11] = {
    0.00102838f, 0.00759876f, 0.03600077f, 0.10936070f, 0.21300553f,
    0.26601172f,
    0.21300553f, 0.10936070f, 0.03600077f, 0.00759876f, 0.00102838f
};

constexpr float C1f  = 1.0e-4f;
constexpr float C2f  = 9.0e-4f;
constexpr float EPSf = 1.0e-12f;

// Interleaved fp16 scratch: one 16-byte record per voxel (f0..f4 + pad).
__device__ uint4 gI[NVOX];
__device__ double g_acc;
__device__ unsigned int g_ticket;

__device__ __forceinline__ int refl(int i) {
    return (i < 0) ? -i : ((i > HD - 1) ? (2 * (HD - 1) - i) : i);
}

// ---------------------------------------------------------------------------
// passDW: fused D-blur (+5 field products) and W-blur, WARP-PRIVATE smem.
// Block = (w-half 80, h, b), 160 threads; warp wi owns d in [32wi, 32wi+32)
// and a private 44-wide (padded 48) slice of each raw row -> no block
// barriers, only __syncwarp. PRE=4 register prefetch per warp.
// ---------------------------------------------------------------------------
__global__ void __launch_bounds__(HD) passDW(const float* __restrict__ src,
                                             const float* __restrict__ ref) {
    __shared__ float S[5][RING][48];
    __shared__ float R[5][RING][48];

    const int t  = threadIdx.x;
    const int wi = t >> 5;
    const int l  = t & 31;
    const int b  = blockIdx.z;
    const int h  = blockIdx.y;
    const int w0 = blockIdx.x * WSEG;

    const size_t bh = ((size_t)(b * HD + h)) * PLN;

    // Warp-slice element map: smem idx i <-> global d' = 32*wi - 6 + i.
    const int gmain = refl(32 * wi - 6 + l);          // smem idx l
    const bool hasx = (l < 12);
    const int gext  = refl(32 * wi + 26 + l);         // smem idx 32 + l

    // Prologue: rows 0..PRE-1 straight into warp-private smem.
    for (int m = 0; m < PRE; ++m) {
        const size_t base = bh + (size_t)refl(w0 - 5 + m) * HD;
        S[wi][m][l] = __ldg(src + base + gmain);
        R[wi][m][l] = __ldg(ref + base + gmain);
        if (hasx) {
            S[wi][m][32 + l] = __ldg(src + base + gext);
            R[wi][m][32 + l] = __ldg(ref + base + gext);
        }
    }
    // Prefetch row PRE into registers.
    float sM, rM, sH = 0.f, rH = 0.f;
    {
        const size_t base = bh + (size_t)refl(w0 - 5 + PRE) * HD;
        sM = __ldg(src + base + gmain);
        rM = __ldg(ref + base + gmain);
        if (hasx) { sH = __ldg(src + base + gext); rH = __ldg(ref + base + gext); }
    }

    // Register ring of D-blurred fields.
    float q0[11], q1[11], q2[11], q3[11], q4[11];

    int scur = 0;        // j % RING
    int spre = PRE;      // (j+PRE) % RING

    #pragma unroll 1
    for (int c = 0; c < 9; ++c) {
        #pragma unroll
        for (int u = 0; u < 11; ++u) {
            const int j = c * 11 + u;
            if (j >= NR) break;
            __syncwarp();

            // Retire prefetched row j+PRE into smem, then prefetch j+PRE+1.
            if (j + PRE < NR) {
                S[wi][spre][l] = sM;
                R[wi][spre][l] = rM;
                if (hasx) { S[wi][spre][32 + l] = sH; R[wi][spre][32 + l] = rH; }
                if (j + PRE + 1 < NR) {
                    const size_t base = bh + (size_t)refl(w0 - 5 + j + PRE + 1) * HD;
                    sM = __ldg(src + base + gmain);
                    rM = __ldg(ref + base + gmain);
                    if (hasx) { sH = __ldg(src + base + gext); rH = __ldg(ref + base + gext); }
                }
            }

            // D-blur row j (slot scur): lane l = d 32wi+l; tap i = l+1+k.
            float a0 = 0.f, a1 = 0.f, a2 = 0.f, a3 = 0.f, a4 = 0.f;
            #pragma unroll
            for (int k = 0; k < 11; ++k) {
                const float s = S[wi][scur][l + 1 + k];
                const float v = R[wi][scur][l + 1 + k];
                const float ss = s * s, vv = v * v, sv = s * v;
                a0 = fmaf(GW[k], s,  a0);
                a1 = fmaf(GW[k], v,  a1);
                a2 = fmaf(GW[k], ss, a2);
                a3 = fmaf(GW[k], vv, a3);
                a4 = fmaf(GW[k], sv, a4);
            }
            q0[u] = a0; q1[u] = a1; q2[u] = a2; q3[u] = a3; q4[u] = a4;

            if (++scur == RING) scur = 0;
            if (++spre == RING) spre = 0;

            // W-blur output w = w0 + j - 10 from ring rows j-10..j.
            if (j >= 10) {
                float m0 = 0.f, m1 = 0.f, m2 = 0.f, m3 = 0.f, m4 = 0.f;
                #pragma unroll
                for (int k = 0; k < 11; ++k) {
                    const int s2 = (u + 1 + k) % 11;
                    m0 = fmaf(GW[k], q0[s2], m0);
                    m1 = fmaf(GW[k], q1[s2], m1);
                    m2 = fmaf(GW[k], q2[s2], m2);
                    m3 = fmaf(GW[k], q3[s2], m3);
                    m4 = fmaf(GW[k], q4[s2], m4);
                }
                uint4 rec;
                *reinterpret_cast<__half2*>(&rec.x) = __floats2half2_rn(m0, m1);
                *reinterpret_cast<__half2*>(&rec.y) = __floats2half2_rn(m2, m3);
                *reinterpret_cast<__half2*>(&rec.z) = __floats2half2_rn(m4, 0.f);
                rec.w = 0u;
                gI[bh + (size_t)(w0 + j - 10) * HD + t] = rec;
            }
        }
    }
}

// ---------------------------------------------------------------------------
// passH: H-blur + SSIM + reduce (R12 form, measured 49.3 us). 12-slot ring,
// one LDG.128 interleaved record per plane. Block (h-seg 80, w, b), 160 thr.
// ---------------------------------------------------------------------------
__global__ void __launch_bounds__(HD) passH(float* __restrict__ out) {
    const int d  = threadIdx.x;
    const int b  = blockIdx.z;
    const int w  = blockIdx.y;
    const int h0 = blockIdx.x * SEG;

    const size_t bw = (size_t)b * VOL + (size_t)w * HD + d;

    float win[5][12];

    #pragma unroll
    for (int m = 0; m < 11; ++m) {
        const uint4 v = __ldg(gI + bw + (size_t)refl(h0 - 5 + m) * PLN);
        const float2 f01 = __half22float2(*reinterpret_cast<const __half2*>(&v.x));
        const float2 f23 = __half22float2(*reinterpret_cast<const __half2*>(&v.y));
        const float2 f4  = __half22float2(*reinterpret_cast<const __half2*>(&v.z));
        win[0][m] = f01.x; win[1][m] = f01.y;
        win[2][m] = f23.x; win[3][m] = f23.y;
        win[4][m] = f4.x;
    }

    float acc = 0.f;

    #pragma unroll 1
    for (int c = 0; c < (SEG + 11) / 12; ++c) {
        const int jbase = c * 12;
        #pragma unroll
        for (int u = 0; u < 12; ++u) {
            const int j = jbase + u;
            if (j >= SEG) break;
            {   // load plane h0+j+6 into slot (u+11)%12 (read next iter, k=10)
                const uint4 v = __ldg(gI + bw + (size_t)refl(h0 + j + 6) * PLN);
                const float2 f01 = __half22float2(*reinterpret_cast<const __half2*>(&v.x));
                const float2 f23 = __half22float2(*reinterpret_cast<const __half2*>(&v.y));
                const float2 f4  = __half22float2(*reinterpret_cast<const __half2*>(&v.z));
                const int sl = (u + 11) % 12;
                win[0][sl] = f01.x; win[1][sl] = f01.y;
                win[2][sl] = f23.x; win[3][sl] = f23.y;
                win[4][sl] = f4.x;
            }
            float mu1 = 0.f, mu2 = 0.f, m11 = 0.f, m22 = 0.f, m12 = 0.f;
            #pragma unroll
            for (int k = 0; k < 11; ++k) {
                const int sl = (u + k) % 12;
                mu1 = fmaf(GW[k], win[0][sl], mu1);
                mu2 = fmaf(GW[k], win[1][sl], mu2);
                m11 = fmaf(GW[k], win[2][sl], m11);
                m22 = fmaf(GW[k], win[3][sl], m22);
                m12 = fmaf(GW[k], win[4][sl], m12);
            }
            const float a  = mu1 * mu1;
            const float bb = mu2 * mu2;
            const float cc = mu1 * mu2;
            const float s1 = m11 - a, s2 = m22 - bb, s12 = m12 - cc;
            const float num = (2.f * cc + C1f) * (2.f * s12 + C2f);
            const float den = (a + bb + C1f) * (s1 + s2 + C2f);
            acc += __fdividef(num, den + EPSf);
        }
    }

    // Reduce: 5 warps -> smem -> atomicAdd(double), ticket finalize.
    float v = acc;
    #pragma unroll
    for (int o = 16; o > 0; o >>= 1) v += __shfl_down_sync(0xffffffffu, v, o);
    __shared__ float ws[5];
    if ((threadIdx.x & 31) == 0) ws[threadIdx.x >> 5] = v;
    __syncthreads();
    if (threadIdx.x == 0) {
        const float s = ws[0] + ws[1] + ws[2] + ws[3] + ws[4];
        atomicAdd(&g_acc, (double)s);
        __threadfence();
        const unsigned done = atomicAdd(&g_ticket, 1u);
        if (done == NBBC - 1) {
            const double vv = atomicAdd(&g_acc, 0.0);
            out[0] = (float)(1.0 - vv / (double)NVOX);
            g_acc = 0.0;
            g_ticket = 0u;
            __threadfence();
        }
    }
}

extern "C" void kernel_launch(void* const* d_in, const int* in_sizes, int n_in,
                              void* d_out, int out_size) {
    const float* src = (const float*)d_in[0];
    const float* ref = (const float*)d_in[1];
    float* out = (float*)d_out;

    passDW<<<dim3(HD / WSEG, HD, 2), HD>>>(src, ref);
    passH<<<dim3(HD / SEG, HD, 2), HD>>>(out);
}

// round 14
// speedup vs baseline: 1.0712x; 1.0712x over previous
#include <cuda_runtime.h>
#include <cuda_fp16.h>

#define HD   160
#define PLN  25600          // W*D
#define VOL  4096000        // H*W*D
#define NVOX 8192000ULL     // 2*160^3
#define WSEG 80             // passDW w-outputs per block
#define NR   90             // rows processed per passDW block (WSEG + 10)
#define PRE  4              // smem prefetch depth (rows)
#define RING 6              // smem row-ring slots
#define SEG  80             // passH slide segment
#define NBBC 640            // passH grid blocks: 2*160*2

typedef unsigned long long ull;

// Normalized 1D Gaussian, KS=11, sigma=1.5
__device__ constexpr float GW[11] = {
    0.00102838f, 0.00759876f, 0.03600077f, 0.10936070f, 0.21300553f,
    0.26601172f,
    0.21300553f, 0.10936070f, 0.03600077f, 0.00759876f, 0.00102838f
};

constexpr float C1f  = 1.0e-4f;
constexpr float C2f  = 9.0e-4f;
constexpr float EPSf = 1.0e-12f;

// Interleaved fp16 scratch: one 16-byte record per voxel (f0..f4 + pad).
__device__ uint4 gI[NVOX];
__device__ double g_acc;
__device__ unsigned int g_ticket;

__device__ __forceinline__ int refl(int i) {
    return (i < 0) ? -i : ((i > HD - 1) ? (2 * (HD - 1) - i) : i);
}

// ---- packed f32x2 helpers (Blackwell 2x FP32) ------------------------------
__device__ __forceinline__ ull pack2(float x, float y) {
    ull r; asm("mov.b64 %0, {%1, %2};" : "=l"(r) : "f"(x), "f"(y)); return r;
}
__device__ __forceinline__ void unpack2(float& x, float& y, ull v) {
    asm("mov.b64 {%0, %1}, %2;" : "=f"(x), "=f"(y) : "l"(v));
}
__device__ __forceinline__ ull fma2(ull a, ull b, ull c) {
    ull d; asm("fma.rn.f32x2 %0, %1, %2, %3;" : "=l"(d) : "l"(a), "l"(b), "l"(c));
    return d;
}
__device__ __forceinline__ ull mul2(ull a, ull b) {
    ull d; asm("mul.rn.f32x2 %0, %1, %2;" : "=l"(d) : "l"(a), "l"(b));
    return d;
}

// ---------------------------------------------------------------------------
// passDW: fused D-blur (+5 field products) and W-blur, f32x2 math.
// Block = (w-half 80, h, b), 160 threads (t = d). Smem rows hold (s,r)
// interleaved -> one LDS.64 per tap. Pairs (a0,a1),(a2,a3) via fma2.
// ---------------------------------------------------------------------------
__global__ void __launch_bounds__(HD) passDW(const float* __restrict__ src,
                                             const float* __restrict__ ref) {
    __shared__ float SR[RING][344];   // 172 (s,r) pairs per row

    const int t  = threadIdx.x;
    const int b  = blockIdx.z;
    const int h  = blockIdx.y;
    const int w0 = blockIdx.x * WSEG;

    const size_t bh = ((size_t)(b * HD + h)) * PLN;

    const bool loT = (t < 6);
    const bool hiT = (t >= 154);
    const int  hpp = loT ? t : (t + 12);             // halo pair index
    const int  hgl = loT ? (6 - t) : (312 - t);      // halo global d

    // Packed weights (GW[k], GW[k]).
    ull W2[11];
    #pragma unroll
    for (int k = 0; k < 11; ++k) W2[k] = pack2(GW[k], GW[k]);

    // Prologue: rows 0..PRE-1 straight into smem (interleaved).
    for (int m = 0; m < PRE; ++m) {
        const size_t base = bh + (size_t)refl(w0 - 5 + m) * HD;
        SR[m][2 * (6 + t)]     = __ldg(src + base + t);
        SR[m][2 * (6 + t) + 1] = __ldg(ref + base + t);
        if (loT || hiT) {
            SR[m][2 * hpp]     = __ldg(src + base + hgl);
            SR[m][2 * hpp + 1] = __ldg(ref + base + hgl);
        }
    }
    // Prefetch row PRE into registers.
    float sM, rM, sH = 0.f, rH = 0.f;
    {
        const size_t base = bh + (size_t)refl(w0 - 5 + PRE) * HD;
        sM = __ldg(src + base + t);
        rM = __ldg(ref + base + t);
        if (loT || hiT) { sH = __ldg(src + base + hgl); rH = __ldg(ref + base + hgl); }
    }

    // Register ring of D-blurred fields: (a0,a1), (a2,a3) packed + a4.
    ull  q01[11], q23[11];
    float q4[11];

    int scur = 0;        // j % RING
    int spre = PRE;      // (j+PRE) % RING

    #pragma unroll 1
    for (int c = 0; c < 9; ++c) {
        #pragma unroll
        for (int u = 0; u < 11; ++u) {
            const int j = c * 11 + u;
            if (j >= NR) break;
            __syncthreads();

            // Retire prefetched row j+PRE into smem, then prefetch j+PRE+1.
            if (j + PRE < NR) {
                SR[spre][2 * (6 + t)]     = sM;
                SR[spre][2 * (6 + t) + 1] = rM;
                if (loT || hiT) { SR[spre][2 * hpp] = sH; SR[spre][2 * hpp + 1] = rH; }
                if (j + PRE + 1 < NR) {
                    const size_t base = bh + (size_t)refl(w0 - 5 + j + PRE + 1) * HD;
                    sM = __ldg(src + base + t);
                    rM = __ldg(ref + base + t);
                    if (loT || hiT) { sH = __ldg(src + base + hgl); rH = __ldg(ref + base + hgl); }
                }
            }

            // D-blur row j (slot scur): one LDS.64 per tap, f32x2 math.
            ull a01 = 0ULL, a23 = 0ULL;
            float a4 = 0.f;
            #pragma unroll
            for (int k = 0; k < 11; ++k) {
                const ull sv = *reinterpret_cast<const ull*>(
                    &SR[scur][2 * (t + 1 + k)]);            // (s, v)
                float s, v; unpack2(s, v, sv);
                const ull ssvv = mul2(sv, sv);              // (s*s, v*v)
                a01 = fma2(W2[k], sv,   a01);               // (blur s, blur v)
                a23 = fma2(W2[k], ssvv, a23);               // (blur ss, blur vv)
                a4  = fmaf(GW[k], s * v, a4);               // blur sv
            }
            q01[u] = a01; q23[u] = a23; q4[u] = a4;

            if (++scur == RING) scur = 0;
            if (++spre == RING) spre = 0;

            // W-blur output w = w0 + j - 10 from ring rows j-10..j.
            if (j >= 10) {
                ull m01 = 0ULL, m23 = 0ULL;
                float m4 = 0.f;
                #pragma unroll
                for (int k = 0; k < 11; ++k) {
                    const int s2 = (u + 1 + k) % 11;
                    m01 = fma2(W2[k], q01[s2], m01);
                    m23 = fma2(W2[k], q23[s2], m23);
                    m4  = fmaf(GW[k], q4[s2], m4);
                }
                float m0, m1, m2, m3;
                unpack2(m0, m1, m01);
                unpack2(m2, m3, m23);
                uint4 rec;
                *reinterpret_cast<__half2*>(&rec.x) = __floats2half2_rn(m0, m1);
                *reinterpret_cast<__half2*>(&rec.y) = __floats2half2_rn(m2, m3);
                *reinterpret_cast<__half2*>(&rec.z) = __floats2half2_rn(m4, 0.f);
                rec.w = 0u;
                gI[bh + (size_t)(w0 + j - 10) * HD + t] = rec;
            }
        }
    }
}

// ---------------------------------------------------------------------------
// passH: H-blur + SSIM + reduce. 12-slot ring, LDG.128 interleaved record,
// f32x2 tap math on the (f0,f1) and (f2,f3) pairs.
// Block (h-seg 80, w, b), 160 threads.
// ---------------------------------------------------------------------------
__global__ void __launch_bounds__(HD) passH(float* __restrict__ out) {
    const int d  = threadIdx.x;
    const int b  = blockIdx.z;
    const int w  = blockIdx.y;
    const int h0 = blockIdx.x * SEG;

    const size_t bw = (size_t)b * VOL + (size_t)w * HD + d;

    ull W2[11];
    #pragma unroll
    for (int k = 0; k < 11; ++k) W2[k] = pack2(GW[k], GW[k]);

    ull  win01[12], win23[12];
    float win4[12];

    #pragma unroll
    for (int m = 0; m < 11; ++m) {
        const uint4 v = __ldg(gI + bw + (size_t)refl(h0 - 5 + m) * PLN);
        const float2 f01 = __half22float2(*reinterpret_cast<const __half2*>(&v.x));
        const float2 f23 = __half22float2(*reinterpret_cast<const __half2*>(&v.y));
        const float2 f4  = __half22float2(*reinterpret_cast<const __half2*>(&v.z));
        win01[m] = pack2(f01.x, f01.y);
        win23[m] = pack2(f23.x, f23.y);
        win4[m]  = f4.x;
    }

    float acc = 0.f;

    #pragma unroll 1
    for (int c = 0; c < (SEG + 11) / 12; ++c) {
        const int jbase = c * 12;
        #pragma unroll
        for (int u = 0; u < 12; ++u) {
            const int j = jbase + u;
            if (j >= SEG) break;
            {   // load plane h0+j+6 into slot (u+11)%12 (read next iter, k=10)
                const uint4 v = __ldg(gI + bw + (size_t)refl(h0 + j + 6) * PLN);
                const float2 f01 = __half22float2(*reinterpret_cast<const __half2*>(&v.x));
                const float2 f23 = __half22float2(*reinterpret_cast<const __half2*>(&v.y));
                const float2 f4  = __half22float2(*reinterpret_cast<const __half2*>(&v.z));
                const int sl = (u + 11) % 12;
                win01[sl] = pack2(f01.x, f01.y);
                win23[sl] = pack2(f23.x, f23.y);
                win4[sl]  = f4.x;
            }
            ull mu12 = 0ULL, mm = 0ULL;
            float m12 = 0.f;
            #pragma unroll
            for (int k = 0; k < 11; ++k) {
                const int sl = (u + k) % 12;
                mu12 = fma2(W2[k], win01[sl], mu12);   // (mu1, mu2)
                mm   = fma2(W2[k], win23[sl], mm);     // (m11, m22)
                m12  = fmaf(GW[k], win4[sl], m12);
            }
            float mu1, mu2, m11, m22;
            unpack2(mu1, mu2, mu12);
            unpack2(m11, m22, mm);

            const float a  = mu1 * mu1;
            const float bb = mu2 * mu2;
            const float cc = mu1 * mu2;
            const float s1 = m11 - a, s2 = m22 - bb, s12 = m12 - cc;
            const float num = (2.f * cc + C1f) * (2.f * s12 + C2f);
            const float den = (a + bb + C1f) * (s1 + s2 + C2f);
            acc += __fdividef(num, den + EPSf);
        }
    }

    // Reduce: 5 warps -> smem -> atomicAdd(double), ticket finalize.
    float v = acc;
    #pragma unroll
    for (int o = 16; o > 0; o >>= 1) v += __shfl_down_sync(0xffffffffu, v, o);
    __shared__ float ws[5];
    if ((threadIdx.x & 31) == 0) ws[threadIdx.x >> 5] = v;
    __syncthreads();
    if (threadIdx.x == 0) {
        const float s = ws[0] + ws[1] + ws[2] + ws[3] + ws[4];
        atomicAdd(&g_acc, (double)s);
        __threadfence();
        const unsigned done = atomicAdd(&g_ticket, 1u);
        if (done == NBBC - 1) {
            const double vv = atomicAdd(&g_acc, 0.0);
            out[0] = (float)(1.0 - vv / (double)NVOX);
            g_acc = 0.0;
            g_ticket = 0u;
            __threadfence();
        }
    }
}

extern "C" void kernel_launch(void* const* d_in, const int* in_sizes, int n_in,
                              void* d_out, int out_size) {
    const float* src = (const float*)d_in[0];
    const float* ref = (const float*)d_in[1];
    float* out = (float*)d_out;

    passDW<<<dim3(HD / WSEG, HD, 2), HD>>>(src, ref);
    passH<<<dim3(HD / SEG, HD, 2), HD>>>(out);
}

// round 15
// speedup vs baseline: 1.0861x; 1.0139x over previous
#include <cuda_runtime.h>
#include <cuda_fp16.h>

#define HD   160
#define PLN  25600          // W*D
#define VOL  4096000        // H*W*D
#define NVOX 8192000ULL     // 2*160^3
#define WSEG 80             // passDW w-outputs per block
#define NR   90             // rows processed per passDW block (WSEG + 10)
#define PRE  4              // smem prefetch depth (rows)
#define RING 6              // smem row-ring slots
#define SEG  80             // passH slide segment
#define NBBC 640            // passH grid blocks: 2*160*2

typedef unsigned long long ull;

// Normalized 1D Gaussian, KS=11, sigma=1.5
__device__ constexpr float GW[11] = {
    0.00102838f, 0.00759876f, 0.03600077f, 0.10936070f, 0.21300553f,
    0.26601172f,
    0.21300553f, 0.10936070f, 0.03600077f, 0.00759876f, 0.00102838f
};

constexpr float C1f  = 1.0e-4f;
constexpr float C2f  = 9.0e-4f;
constexpr float EPSf = 1.0e-12f;

// Interleaved fp16 scratch: one 16-byte record per voxel (f0..f4 + pad).
__device__ uint4 gI[NVOX];
__device__ double g_acc;
__device__ unsigned int g_ticket;

__device__ __forceinline__ int refl(int i) {
    return (i < 0) ? -i : ((i > HD - 1) ? (2 * (HD - 1) - i) : i);
}

// ---- packed f32x2 helpers (for passH) --------------------------------------
__device__ __forceinline__ ull pack2(float x, float y) {
    ull r; asm("mov.b64 %0, {%1, %2};" : "=l"(r) : "f"(x), "f"(y)); return r;
}
__device__ __forceinline__ void unpack2(float& x, float& y, ull v) {
    asm("mov.b64 {%0, %1}, %2;" : "=f"(x), "=f"(y) : "l"(v));
}
__device__ __forceinline__ ull fma2(ull a, ull b, ull c) {
    ull d; asm("fma.rn.f32x2 %0, %1, %2, %3;" : "=l"(d) : "l"(a), "l"(b), "l"(c));
    return d;
}

// ---------------------------------------------------------------------------
// passDW: fused D-blur + W-blur, PRODUCTS PRECOMPUTED IN SMEM.
// When a row is retired into the smem ring, each thread computes its
// element's (s*s, r*r, s*r) ONCE. The D-blur tap is then 3 LDS + 5 FFMA-imm
// (no FMULs). Results bit-identical to the scalar R12 kernel.
// Block = (w-half 80, h, b), 160 threads (t = d).
// ---------------------------------------------------------------------------
__global__ void __launch_bounds__(HD) passDW(const float* __restrict__ src,
                                             const float* __restrict__ ref) {
    __shared__ float2 SR2[RING][172];   // (s, r)
    __shared__ float2 SS2[RING][172];   // (s*s, r*r)
    __shared__ float  SV [RING][172];   // s*r

    const int t  = threadIdx.x;
    const int b  = blockIdx.z;
    const int h  = blockIdx.y;
    const int w0 = blockIdx.x * WSEG;

    const size_t bh = ((size_t)(b * HD + h)) * PLN;

    const bool loT = (t < 6);
    const bool hiT = (t >= 154);
    const bool hasH = loT || hiT;
    const int  hpos = loT ? t : (t + 12);            // halo element index
    const int  hgl  = loT ? (6 - t) : (312 - t);     // halo global d

    // Prologue: rows 0..PRE-1 into smem with products.
    for (int m = 0; m < PRE; ++m) {
        const size_t base = bh + (size_t)refl(w0 - 5 + m) * HD;
        {
            const float s = __ldg(src + base + t);
            const float r = __ldg(ref + base + t);
            SR2[m][6 + t] = make_float2(s, r);
            SS2[m][6 + t] = make_float2(s * s, r * r);
            SV [m][6 + t] = s * r;
        }
        if (hasH) {
            const float s = __ldg(src + base + hgl);
            const float r = __ldg(ref + base + hgl);
            SR2[m][hpos] = make_float2(s, r);
            SS2[m][hpos] = make_float2(s * s, r * r);
            SV [m][hpos] = s * r;
        }
    }
    // Prefetch row PRE into registers.
    float sM, rM, sH = 0.f, rH = 0.f;
    {
        const size_t base = bh + (size_t)refl(w0 - 5 + PRE) * HD;
        sM = __ldg(src + base + t);
        rM = __ldg(ref + base + t);
        if (hasH) { sH = __ldg(src + base + hgl); rH = __ldg(ref + base + hgl); }
    }

    // Register ring of D-blurred fields.
    float q0[11], q1[11], q2[11], q3[11], q4[11];

    int scur = 0;        // j % RING
    int spre = PRE;      // (j+PRE) % RING

    #pragma unroll 1
    for (int c = 0; c < 9; ++c) {
        #pragma unroll
        for (int u = 0; u < 11; ++u) {
            const int j = c * 11 + u;
            if (j >= NR) break;
            __syncthreads();

            // Retire prefetched row (with products), then prefetch next.
            if (j + PRE < NR) {
                SR2[spre][6 + t] = make_float2(sM, rM);
                SS2[spre][6 + t] = make_float2(sM * sM, rM * rM);
                SV [spre][6 + t] = sM * rM;
                if (hasH) {
                    SR2[spre][hpos] = make_float2(sH, rH);
                    SS2[spre][hpos] = make_float2(sH * sH, rH * rH);
                    SV [spre][hpos] = sH * rH;
                }
                if (j + PRE + 1 < NR) {
                    const size_t base = bh + (size_t)refl(w0 - 5 + j + PRE + 1) * HD;
                    sM = __ldg(src + base + t);
                    rM = __ldg(ref + base + t);
                    if (hasH) { sH = __ldg(src + base + hgl); rH = __ldg(ref + base + hgl); }
                }
            }

            // D-blur row j (slot scur): 3 LDS + 5 FFMA-imm per tap.
            float a0 = 0.f, a1 = 0.f, a2 = 0.f, a3 = 0.f, a4 = 0.f;
            #pragma unroll
            for (int k = 0; k < 11; ++k) {
                const float2 sr   = SR2[scur][t + 1 + k];
                const float2 ssvv = SS2[scur][t + 1 + k];
                const float  sv   = SV [scur][t + 1 + k];
                a0 = fmaf(GW[k], sr.x,   a0);
                a1 = fmaf(GW[k], sr.y,   a1);
                a2 = fmaf(GW[k], ssvv.x, a2);
                a3 = fmaf(GW[k], ssvv.y, a3);
                a4 = fmaf(GW[k], sv,     a4);
            }
            q0[u] = a0; q1[u] = a1; q2[u] = a2; q3[u] = a3; q4[u] = a4;

            if (++scur == RING) scur = 0;
            if (++spre == RING) spre = 0;

            // W-blur output w = w0 + j - 10 from ring rows j-10..j.
            if (j >= 10) {
                float m0 = 0.f, m1 = 0.f, m2 = 0.f, m3 = 0.f, m4 = 0.f;
                #pragma unroll
                for (int k = 0; k < 11; ++k) {
                    const int s2 = (u + 1 + k) % 11;
                    m0 = fmaf(GW[k], q0[s2], m0);
                    m1 = fmaf(GW[k], q1[s2], m1);
                    m2 = fmaf(GW[k], q2[s2], m2);
                    m3 = fmaf(GW[k], q3[s2], m3);
                    m4 = fmaf(GW[k], q4[s2], m4);
                }
                uint4 rec;
                *reinterpret_cast<__half2*>(&rec.x) = __floats2half2_rn(m0, m1);
                *reinterpret_cast<__half2*>(&rec.y) = __floats2half2_rn(m2, m3);
                *reinterpret_cast<__half2*>(&rec.z) = __floats2half2_rn(m4, 0.f);
                rec.w = 0u;
                gI[bh + (size_t)(w0 + j - 10) * HD + t] = rec;
            }
        }
    }
}

// ---------------------------------------------------------------------------
// passH: H-blur + SSIM + reduce. 12-slot ring, LDG.128 interleaved record,
// f32x2 tap math (R14 form, measured 48.1 us). Block (h-seg 80, w, b).
// ---------------------------------------------------------------------------
__global__ void __launch_bounds__(HD) passH(float* __restrict__ out) {
    const int d  = threadIdx.x;
    const int b  = blockIdx.z;
    const int w  = blockIdx.y;
    const int h0 = blockIdx.x * SEG;

    const size_t bw = (size_t)b * VOL + (size_t)w * HD + d;

    ull W2[11];
    #pragma unroll
    for (int k = 0; k < 11; ++k) W2[k] = pack2(GW[k], GW[k]);

    ull  win01[12], win23[12];
    float win4[12];

    #pragma unroll
    for (int m = 0; m < 11; ++m) {
        const uint4 v = __ldg(gI + bw + (size_t)refl(h0 - 5 + m) * PLN);
        const float2 f01 = __half22float2(*reinterpret_cast<const __half2*>(&v.x));
        const float2 f23 = __half22float2(*reinterpret_cast<const __half2*>(&v.y));
        const float2 f4  = __half22float2(*reinterpret_cast<const __half2*>(&v.z));
        win01[m] = pack2(f01.x, f01.y);
        win23[m] = pack2(f23.x, f23.y);
        win4[m]  = f4.x;
    }

    float acc = 0.f;

    #pragma unroll 1
    for (int c = 0; c < (SEG + 11) / 12; ++c) {
        const int jbase = c * 12;
        #pragma unroll
        for (int u = 0; u < 12; ++u) {
            const int j = jbase + u;
            if (j >= SEG) break;
            {   // load plane h0+j+6 into slot (u+11)%12 (read next iter, k=10)
                const uint4 v = __ldg(gI + bw + (size_t)refl(h0 + j + 6) * PLN);
                const float2 f01 = __half22float2(*reinterpret_cast<const __half2*>(&v.x));
                const float2 f23 = __half22float2(*reinterpret_cast<const __half2*>(&v.y));
                const float2 f4  = __half22float2(*reinterpret_cast<const __half2*>(&v.z));
                const int sl = (u + 11) % 12;
                win01[sl] = pack2(f01.x, f01.y);
                win23[sl] = pack2(f23.x, f23.y);
                win4[sl]  = f4.x;
            }
            ull mu12 = 0ULL, mm = 0ULL;
            float m12 = 0.f;
            #pragma unroll
            for (int k = 0; k < 11; ++k) {
                const int sl = (u + k) % 12;
                mu12 = fma2(W2[k], win01[sl], mu12);   // (mu1, mu2)
                mm   = fma2(W2[k], win23[sl], mm);     // (m11, m22)
                m12  = fmaf(GW[k], win4[sl], m12);
            }
            float mu1, mu2, m11, m22;
            unpack2(mu1, mu2, mu12);
            unpack2(m11, m22, mm);

            const float a  = mu1 * mu1;
            const float bb = mu2 * mu2;
            const float cc = mu1 * mu2;
            const float s1 = m11 - a, s2 = m22 - bb, s12 = m12 - cc;
            const float num = (2.f * cc + C1f) * (2.f * s12 + C2f);
            const float den = (a + bb + C1f) * (s1 + s2 + C2f);
            acc += __fdividef(num, den + EPSf);
        }
    }

    // Reduce: 5 warps -> smem -> atomicAdd(double), ticket finalize.
    float v = acc;
    #pragma unroll
    for (int o = 16; o > 0; o >>= 1) v += __shfl_down_sync(0xffffffffu, v, o);
    __shared__ float ws[5];
    if ((threadIdx.x & 31) == 0) ws[threadIdx.x >> 5] = v;
    __syncthreads();
    if (threadIdx.x == 0) {
        const float s = ws[0] + ws[1] + ws[2] + ws[3] + ws[4];
        atomicAdd(&g_acc, (double)s);
        __threadfence();
        const unsigned done = atomicAdd(&g_ticket, 1u);
        if (done == NBBC - 1) {
            const double vv = atomicAdd(&g_acc, 0.0);
            out[0] = (float)(1.0 - vv / (double)NVOX);
            g_acc = 0.0;
            g_ticket = 0u;
            __threadfence();
        }
    }
}

extern "C" void kernel_launch(void* const* d_in, const int* in_sizes, int n_in,
                              void* d_out, int out_size) {
    const float* src = (const float*)d_in[0];
    const float* ref = (const float*)d_in[1];
    float* out = (float*)d_out;

    passDW<<<dim3(HD / WSEG, HD, 2), HD>>>(src, ref);
    passH<<<dim3(HD / SEG, HD, 2), HD>>>(out);
}